// round 17
// baseline (speedup 1.0000x reference)
#include <cuda_runtime.h>
#include <cuda_bf16.h>
#include <cstdint>
#include <cstdlib>

// Eager module loading: __device__ globals allocated at context init.
__attribute__((constructor)) static void _force_eager_loading() {
    setenv("CUDA_MODULE_LOADING", "EAGER", 1);
}

#define NN     2048
#define TT     512
#define ROWS_C (NN*TT)        /* 1048576 */
#define ER_C   (NN*(TT-1))    /* 1046528 */
#define BN_EPS 1e-5

#define TPB1   8
#define GRID1  (ROWS_C/(128*TPB1))   /* 1024 */
#define TPB2   8
#define GRID2  (ROWS_C/(128*TPB2))   /* 1024 */
#define NWT    (ROWS_C/32)           /* 32768 warp-tiles */

typedef unsigned long long u64;

// ---- K1 smem float offsets ----
// WF 0..3584, BIAS 3584..3744, XW 3744..6432 (4 x 672: 33 rows x stride 20),
// BO 6432..11040 (4 x 1152)
#define BIAS_F 3584
#define XW_F   3744
#define BO_F   6432
#define K1_TOT 11040          /* 44160 B */
#define BLK_WC_H 0
#define BLK_WC_L 1
#define BLK_W1_H 2
#define BLK_W1_L 4
#define BLK_W2_H 6
#define BLK_W2_L 8
#define BLK_W3_H 10
#define BLK_W3_L 12

// ---- K2 smem float offsets ----
#define NBLK_W1_H 0
#define NBLK_W1_L 2
#define NBLK_W2_H 4
#define NBLK_W2_L 6
#define NBLK_W3_H 8
#define NBLK_W3_L 10
#define NW_BIAS_F 3072
#define NW_SBE_F  3168
#define NW_BO_F   3360
#define NK2_TOT   7968        /* 31872 B */

// ---- device scratch ----
__device__ float g_cf[(size_t)ER_C * 32];
__device__ float g_cb[(size_t)ER_C * 32];
__device__ float g_epart[3][2][32][NWT];    /* 25 MB */
__device__ float g_npart[2][32][NWT];       /* 8.4 MB */
__device__ float g_escale[3][32], g_ebias[3][32];
__device__ float g_nscale[32],    g_nbias[32];

__device__ __forceinline__ float lrelu(float x) { return fmaxf(x, 0.01f * x); }

// ---- bf16 split helpers ----
__device__ __forceinline__ void bsplit(float v, unsigned short& h, unsigned short& l) {
    __nv_bfloat16 hb = __float2bfloat16_rn(v);
    float rest = v - __bfloat162float(hb);
    __nv_bfloat16 lb = __float2bfloat16_rn(rest);
    h = __bfloat16_as_ushort(hb);
    l = __bfloat16_as_ushort(lb);
}
__device__ __forceinline__ void split_pack2(float v0, float v1, uint32_t& hp, uint32_t& lp) {
    asm("cvt.rn.bf16x2.f32 %0, %1, %2;" : "=r"(hp) : "f"(v1), "f"(v0));
    float h0 = __uint_as_float(hp << 16);
    float h1 = __uint_as_float(hp & 0xFFFF0000u);
    float l0 = v0 - h0;
    float l1 = v1 - h1;
    asm("cvt.rn.bf16x2.f32 %0, %1, %2;" : "=r"(lp) : "f"(l1), "f"(l0));
}

// ---- HMMA m16n8k16 bf16 ----
__device__ __forceinline__ void mma4(float* c, const uint32_t* a, uint32_t b0, uint32_t b1) {
    asm volatile(
        "mma.sync.aligned.m16n8k16.row.col.f32.bf16.bf16.f32 "
        "{%0,%1,%2,%3}, {%4,%5,%6,%7}, {%8,%9}, {%0,%1,%2,%3};"
        : "+f"(c[0]), "+f"(c[1]), "+f"(c[2]), "+f"(c[3])
        : "r"(a[0]), "r"(a[1]), "r"(a[2]), "r"(a[3]), "r"(b0), "r"(b1));
}

// one K16-chunk of a 32xN32 layer; 3-product bf16 split
__device__ __forceinline__ void gemm_kc(const uint32_t* __restrict__ WFu,
        int blkH, int blkL, int kc,
        const uint32_t* aH, const uint32_t* aL, int lane, float* C)
{
    const uint4* ph = (const uint4*)(WFu + (blkH + kc) * 256 + lane * 4);
    const uint4* pl = (const uint4*)(WFu + (blkL + kc) * 256 + lane * 4);
    uint4 H0 = ph[0], H1 = ph[32];
    uint4 L0 = pl[0], L1 = pl[32];
#pragma unroll
    for (int mt = 0; mt < 2; mt++) {
        const uint32_t* ah = aH + mt * 4;
        const uint32_t* al = aL + mt * 4;
        float* c = C + mt * 16;
        mma4(c + 0,  ah, H0.x, H0.y); mma4(c + 0,  al, H0.x, H0.y); mma4(c + 0,  ah, L0.x, L0.y);
        mma4(c + 4,  ah, H0.z, H0.w); mma4(c + 4,  al, H0.z, H0.w); mma4(c + 4,  ah, L0.z, L0.w);
        mma4(c + 8,  ah, H1.x, H1.y); mma4(c + 8,  al, H1.x, H1.y); mma4(c + 8,  ah, L1.x, L1.y);
        mma4(c + 12, ah, H1.z, H1.w); mma4(c + 12, al, H1.z, H1.w); mma4(c + 12, ah, L1.z, L1.w);
    }
}

__device__ __forceinline__ void init_C(const float* bias, int t, float* C) {
#pragma unroll
    for (int nt = 0; nt < 4; nt++) {
        float b0 = bias[8 * nt + 2 * t];
        float b1 = bias[8 * nt + 2 * t + 1];
#pragma unroll
        for (int mt = 0; mt < 2; mt++) {
            C[mt*16 + nt*4 + 0] = b0; C[mt*16 + nt*4 + 1] = b1;
            C[mt*16 + nt*4 + 2] = b0; C[mt*16 + nt*4 + 3] = b1;
        }
    }
}

__device__ __forceinline__ void epi_split(const float* C, uint32_t* AH, uint32_t* AL) {
#pragma unroll
    for (int mt = 0; mt < 2; mt++)
#pragma unroll
        for (int kc = 0; kc < 2; kc++) {
            int j0 = 2 * kc, j1 = 2 * kc + 1;
            float v0 = lrelu(C[mt*16 + j0*4 + 0]), v1 = lrelu(C[mt*16 + j0*4 + 1]);
            float v2 = lrelu(C[mt*16 + j0*4 + 2]), v3 = lrelu(C[mt*16 + j0*4 + 3]);
            float u0 = lrelu(C[mt*16 + j1*4 + 0]), u1 = lrelu(C[mt*16 + j1*4 + 1]);
            float u2 = lrelu(C[mt*16 + j1*4 + 2]), u3 = lrelu(C[mt*16 + j1*4 + 3]);
            split_pack2(v0, v1, AH[kc*8 + mt*4 + 0], AL[kc*8 + mt*4 + 0]);
            split_pack2(v2, v3, AH[kc*8 + mt*4 + 1], AL[kc*8 + mt*4 + 1]);
            split_pack2(u0, u1, AH[kc*8 + mt*4 + 2], AL[kc*8 + mt*4 + 2]);
            split_pack2(u2, u3, AH[kc*8 + mt*4 + 3], AL[kc*8 + mt*4 + 3]);
        }
}

// ---------------- K1: HMMA edge chains, 8 tiles/block, warp-independent ----------------
__global__ __launch_bounds__(128, 3) void k_edge_tc(
    const float* __restrict__ x, float* __restrict__ dout,
    const float* __restrict__ eW1, const float* __restrict__ eb1,
    const float* __restrict__ eW2, const float* __restrict__ eb2,
    const float* __restrict__ eW3, const float* __restrict__ eb3)
{
    extern __shared__ float smf[];
    uint32_t* WFu = (uint32_t*)smf;
    const int tid = threadIdx.x, bid = blockIdx.x;
    const int lane = tid & 31, warp = tid >> 5;
    const int g = lane >> 2, t = lane & 3;

    if (tid < 32) {
        float b1v = eb1[tid], wd = eW1[1024 + tid];
        smf[BIAS_F + tid]       = b1v;
        smf[BIAS_F + 32 + tid]  = b1v + wd;
        smf[BIAS_F + 64 + tid]  = b1v - wd;
        smf[BIAS_F + 96 + tid]  = eb2[tid];
        smf[BIAS_F + 128 + tid] = eb3[tid];
    }
    for (int idx = tid; idx < 3584; idx += 128) {
        int blk = idx >> 8;
        int rem = idx & 255;
        int j4 = rem >> 7;
        int ln = (rem >> 2) & 31;
        int q  = rem & 3;
        int gg = ln >> 2, tt = ln & 3;
        int nt = 2 * j4 + (q >> 1);
        int rg = q & 1;
        int n  = 8 * nt + gg;
        int half, kc, which;
        if (blk < 2)       { which = 0; half = blk;          kc = 0; }
        else if (blk < 6)  { which = 1; half = (blk - 2) >> 1;  kc = (blk - 2) & 1; }
        else if (blk < 10) { which = 2; half = (blk - 6) >> 1;  kc = (blk - 6) & 1; }
        else               { which = 3; half = (blk - 10) >> 1; kc = (blk - 10) & 1; }
        int k0 = 16 * kc + 2 * tt + 8 * rg;
        float w0, w1;
        if (which == 0)      { w0 = eW1[k0*32+n] + eW1[(k0+16)*32+n];
                               w1 = eW1[(k0+1)*32+n] + eW1[(k0+17)*32+n]; }
        else if (which == 1) { w0 = eW1[k0*32+n]; w1 = eW1[(k0+1)*32+n]; }
        else if (which == 2) { w0 = eW2[k0*32+n]; w1 = eW2[(k0+1)*32+n]; }
        else                 { w0 = eW3[k0*32+n]; w1 = eW3[(k0+1)*32+n]; }
        unsigned short h0, l0, h1, l1;
        bsplit(w0, h0, l0); bsplit(w1, h1, l1);
        WFu[blk * 256 + j4 * 128 + ln * 4 + q] =
            (half == 0) ? ((uint32_t)h0 | ((uint32_t)h1 << 16))
                        : ((uint32_t)l0 | ((uint32_t)l1 << 16));
    }
    __syncthreads();

    float* xw = smf + XW_F + warp * 672;     // 33 rows x stride 20
    float* bw = smf + BO_F + warp * 1152;
    const float4* X4 = (const float4*)x;

    for (int it = 0; it < TPB1; it++) {
        const int r0w = bid * (128 * TPB1) + it * 128 + warp * 32;
        const int wt = r0w >> 5;             // global warp-tile index

        // per-warp x staging (33 rows, clamped)
        __syncwarp();
        for (int idx = lane; idx < 132; idx += 32) {
            int rrow = r0w + (idx >> 2);
            if (rrow > ROWS_C - 1) rrow = ROWS_C - 1;
            *(float4*)(xw + (idx >> 2) * 20 + (idx & 3) * 4) = X4[(size_t)rrow * 4 + (idx & 3)];
        }
        __syncwarp();

        uint32_t XcH[8], XcL[8], XnH[8], XnL[8];
#pragma unroll
        for (int mt = 0; mt < 2; mt++)
#pragma unroll
            for (int rr = 0; rr < 2; rr++) {
                int rl = mt * 16 + rr * 8 + g;
                float2 vA = *(const float2*)(xw + rl * 20 + 2 * t);
                float2 vB = *(const float2*)(xw + rl * 20 + 2 * t + 8);
                split_pack2(vA.x, vA.y, XcH[mt*4 + rr],     XcL[mt*4 + rr]);
                split_pack2(vB.x, vB.y, XcH[mt*4 + 2 + rr], XcL[mt*4 + 2 + rr]);
                float2 nA = *(const float2*)(xw + (rl + 1) * 20 + 2 * t);
                float2 nB = *(const float2*)(xw + (rl + 1) * 20 + 2 * t + 8);
                split_pack2(nA.x, nA.y, XnH[mt*4 + rr],     XnL[mt*4 + rr]);
                split_pack2(nB.x, nB.y, XnH[mt*4 + 2 + rr], XnL[mt*4 + 2 + rr]);
            }

        uint32_t A2H[16], A2L[16];
        float C[32];

#pragma unroll
        for (int ch = 0; ch < 3; ch++) {
            init_C(smf + BIAS_F + ch * 32, t, C);
            if (ch == 0) {
                gemm_kc(WFu, BLK_WC_H, BLK_WC_L, 0, XcH, XcL, lane, C);
            } else if (ch == 1) {
                gemm_kc(WFu, BLK_W1_H, BLK_W1_L, 0, XnH, XnL, lane, C);
                gemm_kc(WFu, BLK_W1_H, BLK_W1_L, 1, XcH, XcL, lane, C);
            } else {
                gemm_kc(WFu, BLK_W1_H, BLK_W1_L, 0, XcH, XcL, lane, C);
                gemm_kc(WFu, BLK_W1_H, BLK_W1_L, 1, XnH, XnL, lane, C);
            }
            epi_split(C, A2H, A2L);
            init_C(smf + BIAS_F + 96, t, C);
            gemm_kc(WFu, BLK_W2_H, BLK_W2_L, 0, A2H,     A2L,     lane, C);
            gemm_kc(WFu, BLK_W2_H, BLK_W2_L, 1, A2H + 8, A2L + 8, lane, C);
            epi_split(C, A2H, A2L);
            init_C(smf + BIAS_F + 128, t, C);
            gemm_kc(WFu, BLK_W3_H, BLK_W3_L, 0, A2H,     A2L,     lane, C);
            gemm_kc(WFu, BLK_W3_H, BLK_W3_L, 1, A2H + 8, A2L + 8, lane, C);

            __syncwarp();
#pragma unroll
            for (int mt = 0; mt < 2; mt++)
#pragma unroll
                for (int nt = 0; nt < 4; nt++) {
                    int ra = mt * 16 + g, rbx = ra + 8;
                    *(float2*)(bw + ra * 36 + 8 * nt + 2 * t) =
                        make_float2(C[mt*16 + nt*4 + 0], C[mt*16 + nt*4 + 1]);
                    *(float2*)(bw + rbx * 36 + 8 * nt + 2 * t) =
                        make_float2(C[mt*16 + nt*4 + 2], C[mt*16 + nt*4 + 3]);
                }
            __syncwarp();
            // warp-direct stats (lane = channel)
            {
                float s = 0.f, q = 0.f;
#pragma unroll 4
                for (int rl = 0; rl < 32; rl++) {
                    float m = (ch == 0) ? 1.f : ((((r0w + rl) & 511) != 511) ? 1.f : 0.f);
                    float v = bw[rl * 36 + lane] * m;
                    s += v; q += v * v;
                }
                g_epart[ch][0][lane][wt] = s;
                g_epart[ch][1][lane][wt] = q;
            }
            if (ch == 0) {
#pragma unroll
                for (int i = 0; i < 8; i++) {
                    int rl = 4 * i + (lane >> 3);
                    int cc = (lane & 7) * 4;
                    float4 v = *(const float4*)(bw + rl * 36 + cc);
                    *(float4*)(dout + (size_t)(r0w + rl) * 32 + cc) = v;
                }
            } else {
                float* dst = (ch == 1) ? g_cf : g_cb;
#pragma unroll
                for (int i = 0; i < 8; i++) {
                    int rl = 4 * i + (lane >> 3);
                    int gr = r0w + rl;
                    if ((gr & 511) != 511) {
                        int e = gr - (gr >> 9);
                        int cc = (lane & 7) * 4;
                        float4 v = *(const float4*)(bw + rl * 36 + cc);
                        *(float4*)(dst + (size_t)e * 32 + cc) = v;
                    }
                }
            }
        }
    }
}

// ---------------- stats finalize ----------------
__global__ void k_fin_edge(const float* __restrict__ gamma, const float* __restrict__ beta) {
    int arr = blockIdx.x >> 5, c = blockIdx.x & 31;
    int tid = threadIdx.x;
    __shared__ double ss[256], sq[256];
    double sa = 0.0, sb2 = 0.0, qa = 0.0, qb = 0.0;
    const float* ps = &g_epart[arr][0][c][0];
    const float* pz = &g_epart[arr][1][c][0];
    for (int i = tid; i < NWT; i += 512) {
        sa += ps[i]; qa += pz[i];
        sb2 += ps[i + 256]; qb += pz[i + 256];
    }
    ss[tid] = sa + sb2; sq[tid] = qa + qb;
    __syncthreads();
    for (int o = 128; o > 0; o >>= 1) {
        if (tid < o) { ss[tid] += ss[tid + o]; sq[tid] += sq[tid + o]; }
        __syncthreads();
    }
    if (tid == 0) {
        double M   = (arr == 0) ? (double)ROWS_C : (double)ER_C;
        double mu  = ss[0] / M;
        double var = sq[0] / M - mu * mu;
        double inv = 1.0 / sqrt(var + BN_EPS);
        g_escale[arr][c] = (float)((double)gamma[c] * inv);
        g_ebias [arr][c] = (float)((double)beta[c] - mu * (double)gamma[c] * inv);
    }
}

__global__ void k_fin_node(const float* __restrict__ gamma, const float* __restrict__ beta) {
    int c = blockIdx.x;
    int tid = threadIdx.x;
    __shared__ double ss[256], sq[256];
    double sa = 0.0, sb2 = 0.0, qa = 0.0, qb = 0.0;
    const float* ps = &g_npart[0][c][0];
    const float* pz = &g_npart[1][c][0];
    for (int i = tid; i < NWT; i += 512) {
        sa += ps[i]; qa += pz[i];
        sb2 += ps[i + 256]; qb += pz[i + 256];
    }
    ss[tid] = sa + sb2; sq[tid] = qa + qb;
    __syncthreads();
    for (int o = 128; o > 0; o >>= 1) {
        if (tid < o) { ss[tid] += ss[tid + o]; sq[tid] += sq[tid + o]; }
        __syncthreads();
    }
    if (tid == 0) {
        double M   = (double)ROWS_C;
        double mu  = ss[0] / M;
        double var = sq[0] / M - mu * mu;
        double inv = 1.0 / sqrt(var + BN_EPS);
        g_nscale[c] = (float)((double)gamma[c] * inv);
        g_nbias [c] = (float)((double)beta[c] - mu * (double)gamma[c] * inv);
    }
}

// ---------------- K2: HMMA aggregate + node MLP, 8 tiles/block ----------------
__global__ __launch_bounds__(128, 4) void k_node_tc(
    float* __restrict__ dout,
    const float* __restrict__ nW1, const float* __restrict__ nb1,
    const float* __restrict__ nW2, const float* __restrict__ nb2,
    const float* __restrict__ nW3, const float* __restrict__ nb3)
{
    extern __shared__ float smf[];
    uint32_t* WFu = (uint32_t*)smf;
    const int tid = threadIdx.x, bid = blockIdx.x;
    const int lane = tid & 31, warp = tid >> 5;
    const int g = lane >> 2, t = lane & 3;

    if (tid < 32) {
        smf[NW_BIAS_F + tid]      = nb1[tid];
        smf[NW_BIAS_F + 32 + tid] = nb2[tid];
        smf[NW_BIAS_F + 64 + tid] = nb3[tid];
    }
    for (int i = tid; i < 192; i += 128) {
        int arr = i / 64, sb3 = (i >> 5) & 1, c = i & 31;
        smf[NW_SBE_F + i] = sb3 ? g_ebias[arr][c] : g_escale[arr][c];
    }
    for (int idx = tid; idx < 3072; idx += 128) {
        int blk = idx >> 8;
        int rem = idx & 255;
        int j4 = rem >> 7;
        int ln = (rem >> 2) & 31;
        int q  = rem & 3;
        int gg = ln >> 2, tt = ln & 3;
        int nt = 2 * j4 + (q >> 1);
        int rg = q & 1;
        int n  = 8 * nt + gg;
        int which = blk >> 2;
        int sub = blk & 3;
        int half = sub >> 1, kc = sub & 1;
        int k0 = 16 * kc + 2 * tt + 8 * rg;
        const float* W = (which == 0) ? nW1 : (which == 1) ? nW2 : nW3;
        float w0 = W[k0 * 32 + n], w1 = W[(k0 + 1) * 32 + n];
        unsigned short h0, l0, h1, l1;
        bsplit(w0, h0, l0); bsplit(w1, h1, l1);
        WFu[blk * 256 + j4 * 128 + ln * 4 + q] =
            (half == 0) ? ((uint32_t)h0 | ((uint32_t)h1 << 16))
                        : ((uint32_t)l0 | ((uint32_t)l1 << 16));
    }
    __syncthreads();

    const float* s0 = smf + NW_SBE_F;       const float* b0 = smf + NW_SBE_F + 32;
    const float* s1 = smf + NW_SBE_F + 64;  const float* b1 = smf + NW_SBE_F + 96;
    const float* s2 = smf + NW_SBE_F + 128; const float* b2 = smf + NW_SBE_F + 160;

    float* bw = smf + NW_BO_F + warp * 1152;
    const int c0 = 8 * t;

    for (int it = 0; it < TPB2; it++) {
        const int r0w = bid * (128 * TPB2) + it * 128 + warp * 32;
        const int wt = r0w >> 5;

        __syncwarp();
        // ---- aggregation into bounce ----
#pragma unroll
        for (int rr = 0; rr < 4; rr++) {
            int rl = 4 * g + rr;
            int r = r0w + rl;
            int n0r = r >> 9;
            int tt2 = r & 511;
            float mf = (tt2 != 0)   ? 1.f : 0.f;
            float mb = (tt2 != 511) ? 1.f : 0.f;
            float a[8];

            const float4* ip = (const float4*)dout + (size_t)r * 8 + t * 2;
            float4 va = ip[0], vb = ip[1];
            a[0] = s0[c0+0]*va.x + b0[c0+0]; a[1] = s0[c0+1]*va.y + b0[c0+1];
            a[2] = s0[c0+2]*va.z + b0[c0+2]; a[3] = s0[c0+3]*va.w + b0[c0+3];
            a[4] = s0[c0+4]*vb.x + b0[c0+4]; a[5] = s0[c0+5]*vb.y + b0[c0+5];
            a[6] = s0[c0+6]*vb.z + b0[c0+6]; a[7] = s0[c0+7]*vb.w + b0[c0+7];
            {
                long e = (long)r - n0r - 1; if (e < 0) e = 0;
                const float4* fp = (const float4*)(g_cf + (size_t)e * 32 + c0);
                float4 fa = fp[0], fb = fp[1];
                a[0] += mf * (s1[c0+0]*fa.x + b1[c0+0]);
                a[1] += mf * (s1[c0+1]*fa.y + b1[c0+1]);
                a[2] += mf * (s1[c0+2]*fa.z + b1[c0+2]);
                a[3] += mf * (s1[c0+3]*fa.w + b1[c0+3]);
                a[4] += mf * (s1[c0+4]*fb.x + b1[c0+4]);
                a[5] += mf * (s1[c0+5]*fb.y + b1[c0+5]);
                a[6] += mf * (s1[c0+6]*fb.z + b1[c0+6]);
                a[7] += mf * (s1[c0+7]*fb.w + b1[c0+7]);
            }
            {
                long e = (long)r - n0r; if (e > ER_C - 1) e = ER_C - 1;
                const float4* bp = (const float4*)(g_cb + (size_t)e * 32 + c0);
                float4 ba = bp[0], bb = bp[1];
                a[0] += mb * (s2[c0+0]*ba.x + b2[c0+0]);
                a[1] += mb * (s2[c0+1]*ba.y + b2[c0+1]);
                a[2] += mb * (s2[c0+2]*ba.z + b2[c0+2]);
                a[3] += mb * (s2[c0+3]*ba.w + b2[c0+3]);
                a[4] += mb * (s2[c0+4]*bb.x + b2[c0+4]);
                a[5] += mb * (s2[c0+5]*bb.y + b2[c0+5]);
                a[6] += mb * (s2[c0+6]*bb.z + b2[c0+6]);
                a[7] += mb * (s2[c0+7]*bb.w + b2[c0+7]);
            }
            *(float4*)(bw + rl * 36 + c0)     = make_float4(a[0], a[1], a[2], a[3]);
            *(float4*)(bw + rl * 36 + c0 + 4) = make_float4(a[4], a[5], a[6], a[7]);
        }
        __syncwarp();

        uint32_t AH[16], AL[16];
#pragma unroll
        for (int mt = 0; mt < 2; mt++)
#pragma unroll
            for (int rr = 0; rr < 2; rr++) {
                int rl = mt * 16 + rr * 8 + g;
#pragma unroll
                for (int kc = 0; kc < 2; kc++) {
                    float2 vA = *(const float2*)(bw + rl * 36 + 16 * kc + 2 * t);
                    float2 vB = *(const float2*)(bw + rl * 36 + 16 * kc + 2 * t + 8);
                    split_pack2(vA.x, vA.y, AH[kc*8 + mt*4 + rr],     AL[kc*8 + mt*4 + rr]);
                    split_pack2(vB.x, vB.y, AH[kc*8 + mt*4 + 2 + rr], AL[kc*8 + mt*4 + 2 + rr]);
                }
            }

        float C[32];
        init_C(smf + NW_BIAS_F, t, C);
        gemm_kc(WFu, NBLK_W1_H, NBLK_W1_L, 0, AH,     AL,     lane, C);
        gemm_kc(WFu, NBLK_W1_H, NBLK_W1_L, 1, AH + 8, AL + 8, lane, C);
        epi_split(C, AH, AL);
        init_C(smf + NW_BIAS_F + 32, t, C);
        gemm_kc(WFu, NBLK_W2_H, NBLK_W2_L, 0, AH,     AL,     lane, C);
        gemm_kc(WFu, NBLK_W2_H, NBLK_W2_L, 1, AH + 8, AL + 8, lane, C);
        epi_split(C, AH, AL);
        init_C(smf + NW_BIAS_F + 64, t, C);
        gemm_kc(WFu, NBLK_W3_H, NBLK_W3_L, 0, AH,     AL,     lane, C);
        gemm_kc(WFu, NBLK_W3_H, NBLK_W3_L, 1, AH + 8, AL + 8, lane, C);

        __syncwarp();
#pragma unroll
        for (int mt = 0; mt < 2; mt++)
#pragma unroll
            for (int nt = 0; nt < 4; nt++) {
                int ra = mt * 16 + g, rbx = ra + 8;
                *(float2*)(bw + ra * 36 + 8 * nt + 2 * t) =
                    make_float2(C[mt*16 + nt*4 + 0], C[mt*16 + nt*4 + 1]);
                *(float2*)(bw + rbx * 36 + 8 * nt + 2 * t) =
                    make_float2(C[mt*16 + nt*4 + 2], C[mt*16 + nt*4 + 3]);
            }
        __syncwarp();
        {
            float s = 0.f, q = 0.f;
#pragma unroll 4
            for (int rl = 0; rl < 32; rl++) {
                float v = bw[rl * 36 + lane];
                s += v; q += v * v;
            }
            g_npart[0][lane][wt] = s;
            g_npart[1][lane][wt] = q;
        }
#pragma unroll
        for (int i = 0; i < 8; i++) {
            int rl = 4 * i + (lane >> 3);
            int cc = (lane & 7) * 4;
            float4 v = *(const float4*)(bw + rl * 36 + cc);
            *(float4*)(dout + (size_t)(r0w + rl) * 32 + cc) = v;
        }
    }
}

// ---------------- K3: normalize in place ----------------
__global__ __launch_bounds__(256) void k_final(float* __restrict__ dout) {
    __shared__ float sc[32], bi[32];
    int tid = threadIdx.x;
    if (tid < 32) { sc[tid] = g_nscale[tid]; bi[tid] = g_nbias[tid]; }
    __syncthreads();
    int lane = tid & 31;
    int s = lane & 3;
    int r = (blockIdx.x * 256 + tid) >> 2;
    int c0 = s * 8;
    float4* D4 = reinterpret_cast<float4*>(dout);
    float4 va = D4[(size_t)r * 8 + s * 2];
    float4 vb = D4[(size_t)r * 8 + s * 2 + 1];
    va.x = va.x * sc[c0 + 0] + bi[c0 + 0]; va.y = va.y * sc[c0 + 1] + bi[c0 + 1];
    va.z = va.z * sc[c0 + 2] + bi[c0 + 2]; va.w = va.w * sc[c0 + 3] + bi[c0 + 3];
    vb.x = vb.x * sc[c0 + 4] + bi[c0 + 4]; vb.y = vb.y * sc[c0 + 5] + bi[c0 + 5];
    vb.z = vb.z * sc[c0 + 6] + bi[c0 + 6]; vb.w = vb.w * sc[c0 + 7] + bi[c0 + 7];
    D4[(size_t)r * 8 + s * 2]     = va;
    D4[(size_t)r * 8 + s * 2 + 1] = vb;
}

// ---------------- launch ----------------
extern "C" void kernel_launch(void* const* d_in, const int* in_sizes, int n_in,
                              void* d_out, int out_size)
{
    const float* x    = (const float*)d_in[0];
    const float* eW1  = (const float*)d_in[1];
    const float* eb1  = (const float*)d_in[2];
    const float* eW2  = (const float*)d_in[3];
    const float* eb2  = (const float*)d_in[4];
    const float* eW3  = (const float*)d_in[5];
    const float* eb3  = (const float*)d_in[6];
    const float* eg   = (const float*)d_in[7];
    const float* ebt  = (const float*)d_in[8];
    const float* nW1  = (const float*)d_in[9];
    const float* nb1  = (const float*)d_in[10];
    const float* nW2  = (const float*)d_in[11];
    const float* nb2  = (const float*)d_in[12];
    const float* nW3  = (const float*)d_in[13];
    const float* nb3  = (const float*)d_in[14];
    const float* ng   = (const float*)d_in[15];
    const float* nbt  = (const float*)d_in[16];
    float* out = (float*)d_out;

    cudaFuncSetAttribute(k_edge_tc, cudaFuncAttributeMaxDynamicSharedMemorySize, K1_TOT * 4);
    cudaFuncSetAttribute(k_node_tc, cudaFuncAttributeMaxDynamicSharedMemorySize, NK2_TOT * 4);

    k_edge_tc<<<GRID1, 128, K1_TOT * 4>>>(x, out, eW1, eb1, eW2, eb2, eW3, eb3);
    k_fin_edge<<<96, 256>>>(eg, ebt);
    k_node_tc<<<GRID2, 128, NK2_TOT * 4>>>(out, nW1, nb1, nW2, nb2, nW3, nb3);
    k_fin_node<<<32, 256>>>(ng, nbt);
    k_final<<<ROWS_C * 4 / 256, 256>>>(out);
}